// round 13
// baseline (speedup 1.0000x reference)
#include <cuda_runtime.h>
#include <math.h>

#define Bn 16
#define Cn 3
#define Hn 512
#define Wn 512
#define HW (Hn * Wn)           // 262144
#define CHW (Cn * HW)          // 786432
#define NTOT (Bn * Cn * HW)    // 12582912

#define NCHUNK 4
#define BPC (Bn / NCHUNK)      // 4 batches per chunk

// ---- K1: pure streaming residual (measured 6.26 TB/s) ----
#define K1_THREADS 256
#define K1_PX_PER_BLOCK (K1_THREADS * 8)   // 2048
#define K1_BPB (HW / K1_PX_PER_BLOCK)      // 128
#define K1_NBLK (K1_BPB * Bn)              // 2048
#define K1_CHUNK_BLOCKS (K1_BPB * BPC)     // 512

// ---- K2: vectorized stencil over r_det ----
#define TW 64
#define TH 64
#define HTH (TH + 2)           // 66
#define HTW 68                 // padded; idx k = gcol (w0-1+k), valid k in [0,66)
#define HTW_VALID 66
#define VPR 18
#define NITEMS (HTH * VPR)     // 1188
#define K2_THREADS 512
#define GX (Wn / TW)           // 8
#define GY (Hn / TH)           // 8
#define K2_BPB (GX * GY)       // 64
#define K2_NBLK (K2_BPB * Bn)  // 1024

__device__ float g_rdet[Bn * HW];
__device__ float g_p1sum[K1_NBLK];
__device__ float g_p1sq[K1_NBLK];
__device__ float g_p2S[K2_NBLK];
__device__ unsigned int g_count;     // zero-init; last K2 block resets

__device__ __forceinline__ int reflect(int i, int n) {
    return (i < 0) ? -i : ((i >= n) ? 2 * n - 2 - i : i);
}
__device__ __forceinline__ float sgnsel(float rs, float re) {
    return (rs < re) ? __int_as_float(__float_as_int(rs) | 0x80000000u) : rs;
}

// ===========================================================================
// K1: streaming signed residual + per-block partials. boff = first batch.
// ===========================================================================
__global__ __launch_bounds__(K1_THREADS) void residual_kernel(
    const float* __restrict__ sr,
    const float* __restrict__ srema,
    const float* __restrict__ hr,
    int boff)
{
    const int tid   = threadIdx.x;
    const int bid   = blockIdx.x;          // 0..511 within chunk
    const int b     = boff + (bid >> 7);
    const int chunk = bid & 127;
    const int base  = b * CHW;
    const int p0    = chunk * K1_PX_PER_BLOCK;

    float lsum = 0.f, lsq = 0.f;
#pragma unroll
    for (int k = 0; k < 2; ++k) {
        const int p  = p0 + (tid + k * K1_THREADS) * 4;
        const int ix = base + p;

        float4 h0v = __ldg((const float4*)(hr    + ix));
        float4 s0v = __ldg((const float4*)(sr    + ix));
        float4 e0v = __ldg((const float4*)(srema + ix));
        float4 h1v = __ldg((const float4*)(hr    + ix + HW));
        float4 s1v = __ldg((const float4*)(sr    + ix + HW));
        float4 e1v = __ldg((const float4*)(srema + ix + HW));
        float4 h2v = __ldg((const float4*)(hr    + ix + 2 * HW));
        float4 s2v = __ldg((const float4*)(sr    + ix + 2 * HW));
        float4 e2v = __ldg((const float4*)(srema + ix + 2 * HW));

        float4 o4;
        {
            float rs = fabsf(h0v.x-s0v.x) + fabsf(h1v.x-s1v.x) + fabsf(h2v.x-s2v.x);
            float re = fabsf(h0v.x-e0v.x) + fabsf(h1v.x-e1v.x) + fabsf(h2v.x-e2v.x);
            o4.x = sgnsel(rs, re); lsum += rs; lsq += rs * rs;
        }
        {
            float rs = fabsf(h0v.y-s0v.y) + fabsf(h1v.y-s1v.y) + fabsf(h2v.y-s2v.y);
            float re = fabsf(h0v.y-e0v.y) + fabsf(h1v.y-e1v.y) + fabsf(h2v.y-e2v.y);
            o4.y = sgnsel(rs, re); lsum += rs; lsq += rs * rs;
        }
        {
            float rs = fabsf(h0v.z-s0v.z) + fabsf(h1v.z-s1v.z) + fabsf(h2v.z-s2v.z);
            float re = fabsf(h0v.z-e0v.z) + fabsf(h1v.z-e1v.z) + fabsf(h2v.z-e2v.z);
            o4.z = sgnsel(rs, re); lsum += rs; lsq += rs * rs;
        }
        {
            float rs = fabsf(h0v.w-s0v.w) + fabsf(h1v.w-s1v.w) + fabsf(h2v.w-s2v.w);
            float re = fabsf(h0v.w-e0v.w) + fabsf(h1v.w-e1v.w) + fabsf(h2v.w-e2v.w);
            o4.w = sgnsel(rs, re); lsum += rs; lsq += rs * rs;
        }
        *(float4*)(g_rdet + b * HW + p) = o4;
    }

    __shared__ float wsum[8], wsq[8];
#pragma unroll
    for (int o = 16; o > 0; o >>= 1) {
        lsum += __shfl_down_sync(0xffffffffu, lsum, o);
        lsq  += __shfl_down_sync(0xffffffffu, lsq,  o);
    }
    const int warp = tid >> 5;
    if ((tid & 31) == 0) { wsum[warp] = lsum; wsq[warp] = lsq; }
    __syncthreads();
    if (tid == 0) {
        float a = 0.f, c = 0.f;
#pragma unroll
        for (int i = 0; i < 8; ++i) { a += wsum[i]; c += wsq[i]; }
        g_p1sum[b * K1_BPB + chunk] = a;
        g_p1sq[b * K1_BPB + chunk]  = c;
    }
}

__device__ __forceinline__ void store4(float* __restrict__ row, int v,
                                       float x, float y, float z, float w) {
    const int i0 = 4 * v - 3;
    if (i0     >= 0 && i0     < HTW_VALID) row[i0]     = x;
    if (i0 + 1 >= 0 && i0 + 1 < HTW_VALID) row[i0 + 1] = y;
    if (i0 + 2 >= 0 && i0 + 2 < HTW_VALID) row[i0 + 2] = z;
    if (i0 + 3 < HTW_VALID)                row[i0 + 3] = w;
}

__device__ __forceinline__ void rowsums(float4 a, float4 b2, float* A, float* B) {
    float p0 = fabsf(a.x), p1 = fabsf(a.y), p2 = fabsf(a.z);
    float p3 = fabsf(a.w), p4 = fabsf(b2.x), p5 = fabsf(b2.y);
    float q0 = p0 * p0, q1 = p1 * p1, q2 = p2 * p2;
    float q3 = p3 * p3, q4 = p4 * p4, q5 = p5 * p5;
    A[0] = p0 + p1 + p2;  A[1] = p1 + p2 + p3;
    A[2] = p2 + p3 + p4;  A[3] = p3 + p4 + p5;
    B[0] = q0 + q1 + q2;  B[1] = q1 + q2 + q3;
    B[2] = q2 + q3 + q4;  B[3] = q3 + q4 + q5;
}

// ===========================================================================
// K2: stencil + last-block finalize. boff = first batch of this chunk.
// ===========================================================================
__global__ __launch_bounds__(K2_THREADS) void loss_kernel(float* __restrict__ out,
                                                          int boff)
{
    __shared__ float rt[HTH * HTW];

    const int tid = threadIdx.x;
    const int w0  = blockIdx.x * TW;
    const int h0  = blockIdx.y * TH;
    const int b   = boff + blockIdx.z;
    const float* __restrict__ rd = g_rdet + b * HW;

    const bool interior = (blockIdx.x > 0 && blockIdx.x < GX - 1);
#pragma unroll
    for (int k = 0; k < 3; ++k) {
        const int t = tid + k * K2_THREADS;
        if (k == 2 && t >= NITEMS) break;
        const int ty  = t / VPR;
        const int v   = t - ty * VPR;
        const int gh  = reflect(h0 - 1 + ty, Hn);
        const int gw0 = w0 - 4 + 4 * v;
        float4 o4;
        if (interior || (gw0 >= 0 && gw0 + 3 < Wn)) {
            o4 = __ldg((const float4*)(rd + gh * Wn + gw0));
        } else {
            o4.x = __ldg(rd + gh * Wn + reflect(gw0,     Wn));
            o4.y = __ldg(rd + gh * Wn + reflect(gw0 + 1, Wn));
            o4.z = __ldg(rd + gh * Wn + reflect(gw0 + 2, Wn));
            o4.w = __ldg(rd + gh * Wn + reflect(gw0 + 3, Wn));
        }
        store4(rt + ty * HTW, v, o4.x, o4.y, o4.z, o4.w);
    }
    __syncthreads();

    float lS = 0.f;
#pragma unroll
    for (int k = 0; k < 2; ++k) {
        const int g  = tid + k * K2_THREADS;
        const int r  = g >> 4;
        const int c0 = (g & 15) << 2;
        const float* bp = rt + r * HTW + c0;

        float4 t0a = *(const float4*)(bp);
        float4 t0b = *(const float4*)(bp + 4);
        float4 t1a = *(const float4*)(bp + HTW);
        float4 t1b = *(const float4*)(bp + HTW + 4);
        float4 t2a = *(const float4*)(bp + 2 * HTW);
        float4 t2b = *(const float4*)(bp + 2 * HTW + 4);

        float A0[4], B0[4], A1[4], B1[4], A2[4], B2[4];
        rowsums(t0a, t0b, A0, B0);
        rowsums(t1a, t1b, A1, B1);
        rowsums(t2a, t2b, A2, B2);

        const float cen[4] = { t1a.y, t1a.z, t1a.w, t1b.x };
#pragma unroll
        for (int x = 0; x < 4; ++x) {
            float s  = A0[x] + A1[x] + A2[x];
            float sq = B0[x] + B1[x] + B2[x];
            float lv = (sq - s * s * (1.0f / 9.0f)) * (1.0f / 8.0f);
            float r4 = fabsf(cen[x]);
            lS += signbit(cen[x]) ? 0.0f : fabsf(lv) * r4;
        }
    }

    __shared__ float wS[16];
#pragma unroll
    for (int o = 16; o > 0; o >>= 1)
        lS += __shfl_down_sync(0xffffffffu, lS, o);
    const int warp = tid >> 5;
    const int lane = tid & 31;
    if (lane == 0) wS[warp] = lS;
    __syncthreads();

    __shared__ bool isLast;
    if (tid == 0) {
        float d = 0.f;
#pragma unroll
        for (int i = 0; i < 16; ++i) d += wS[i];
        g_p2S[blockIdx.x + GX * blockIdx.y + K2_BPB * b] = d;
        __threadfence();
        unsigned prev = atomicAdd(&g_count, 1u);
        isLast = (prev == K2_NBLK - 1);
    }
    __syncthreads();

    if (isLast) {
        if (tid == 0) g_count = 0;
        __shared__ float sres[Bn];
        const int bb = warp;
        float s = 0.f, sq = 0.f, S = 0.f;
#pragma unroll
        for (int e = 0; e < 4; ++e) {
            const int i1 = bb * K1_BPB + lane * 4 + e;
            s  += __ldcg(&g_p1sum[i1]);
            sq += __ldcg(&g_p1sq[i1]);
        }
#pragma unroll
        for (int e = 0; e < 2; ++e) {
            const int i2 = bb * K2_BPB + lane * 2 + e;
            S += __ldcg(&g_p2S[i2]);
        }
#pragma unroll
        for (int o = 16; o > 0; o >>= 1) {
            s  += __shfl_down_sync(0xffffffffu, s,  o);
            sq += __shfl_down_sync(0xffffffffu, sq, o);
            S  += __shfl_down_sync(0xffffffffu, S,  o);
        }
        if (lane == 0) {
            const float n = (float)HW;
            float var = (sq - s * s / n) / (n - 1.0f);
            float w = (var > 0.0f) ? exp2f(0.2f * log2f(var)) : 0.0f;
            sres[bb] = w * S;
        }
        __syncthreads();
        if (tid == 0) {
            float acc = 0.f;
#pragma unroll
            for (int i = 0; i < Bn; ++i) acc += sres[i];
            double Kd = pow(255.0, -2.4) / (double)NTOT;
            out[0] = (float)((double)acc * Kd);
        }
    }
}

// ---------------------------------------------------------------------------
// Software pipeline across batch chunks: K1 chunks on the main (capture)
// stream, K2 chunks on a side stream gated by events. Streams/events created
// once on the first (non-captured correctness) call; capture records the
// fork/join as graph dependencies.
extern "C" void kernel_launch(void* const* d_in, const int* in_sizes, int n_in,
                              void* d_out, int out_size) {
    const float* sr    = (const float*)d_in[0];
    const float* srema = (const float*)d_in[1];
    const float* hr    = (const float*)d_in[2];
    float* out = (float*)d_out;

    static cudaStream_t s_side = nullptr;
    static cudaEvent_t ev_fork[NCHUNK];
    static cudaEvent_t ev_join;
    if (s_side == nullptr) {
        cudaStreamCreateWithFlags(&s_side, cudaStreamNonBlocking);
        for (int i = 0; i < NCHUNK; ++i)
            cudaEventCreateWithFlags(&ev_fork[i], cudaEventDisableTiming);
        cudaEventCreateWithFlags(&ev_join, cudaEventDisableTiming);
    }

    dim3 k2blk(K2_THREADS, 1, 1);
    dim3 k2grd(GX, GY, BPC);

    for (int c = 0; c < NCHUNK; ++c) {
        const int boff = c * BPC;
        residual_kernel<<<K1_CHUNK_BLOCKS, K1_THREADS, 0, 0>>>(sr, srema, hr, boff);
        cudaEventRecord(ev_fork[c], 0);
        cudaStreamWaitEvent(s_side, ev_fork[c], 0);
        loss_kernel<<<k2grd, k2blk, 0, s_side>>>(out, boff);
    }
    cudaEventRecord(ev_join, s_side);
    cudaStreamWaitEvent(0, ev_join, 0);
}

// round 14
// speedup vs baseline: 1.2949x; 1.2949x over previous
#include <cuda_runtime.h>
#include <math.h>

#define Bn 16
#define Cn 3
#define Hn 512
#define Wn 512
#define HW (Hn * Wn)           // 262144
#define CHW (Cn * HW)          // 786432
#define NTOT (Bn * Cn * HW)    // 12582912

#define RPB 16                 // owned image rows per block
#define HR (RPB + 2)           // 18 smem rows (1 halo above, 1 below)
#define NTHREADS 256
#define RBLK (Hn / RPB)        // 32 row-blocks per image
#define NBLK (RBLK * Bn)       // 512 blocks total
#define VPW (Wn / 4)           // 128 float4 groups per row

// Phase-1 items: HR rows * VPW groups = 2304 = 9 * 256  (exact)
// Phase-2 items: RPB rows * VPW groups = 2048 = 8 * 256 (exact)

__device__ float g_psum[NBLK];   // per-block sum(r_raw) over owned pixels
__device__ float g_psq[NBLK];    // per-block sum(r_raw^2)
__device__ float g_pS[NBLK];     // per-block sum(|lv_raw| * r_raw * mask)
__device__ unsigned int g_count; // zero-init; last block resets to 0

__device__ __forceinline__ int reflect(int i, int n) {
    return (i < 0) ? -i : ((i >= n) ? 2 * n - 2 - i : i);
}
__device__ __forceinline__ float sgnsel(float rs, float re) {
    // signed residual: sign bit set iff rs < re (mask). rs >= 0 always.
    return (rs < re) ? __int_as_float(__float_as_int(rs) | 0x80000000u) : rs;
}

__global__ __launch_bounds__(NTHREADS) void fused_kernel(
    const float* __restrict__ sr,
    const float* __restrict__ srema,
    const float* __restrict__ hr,
    float* __restrict__ out)
{
    __shared__ float rt[HR][Wn];   // 36 KB: signed raw residuals, full-width rows

    const int tid = threadIdx.x;
    const int bid = blockIdx.x;
    const int b   = bid >> 5;      // batch
    const int rb  = bid & 31;      // row-block within image
    const int h0  = rb * RPB;
    const int base = b * CHW;

    // --- Phase 1: residual for 18 full-width rows (contiguous streaming) ----
#pragma unroll
    for (int k = 0; k < 9; ++k) {
        const int t   = tid + k * NTHREADS;   // 0..2303
        const int row = t >> 7;               // smem row 0..17
        const int v   = t & 127;              // float4 group in row
        const int gh  = reflect(h0 - 1 + row, Hn);
        const int ix  = base + gh * Wn + 4 * v;

        float4 h0v = __ldg((const float4*)(hr    + ix));
        float4 s0v = __ldg((const float4*)(sr    + ix));
        float4 e0v = __ldg((const float4*)(srema + ix));
        float4 h1v = __ldg((const float4*)(hr    + ix + HW));
        float4 s1v = __ldg((const float4*)(sr    + ix + HW));
        float4 e1v = __ldg((const float4*)(srema + ix + HW));
        float4 h2v = __ldg((const float4*)(hr    + ix + 2 * HW));
        float4 s2v = __ldg((const float4*)(sr    + ix + 2 * HW));
        float4 e2v = __ldg((const float4*)(srema + ix + 2 * HW));

        float4 o4;
        {
            float rs = fabsf(h0v.x-s0v.x) + fabsf(h1v.x-s1v.x) + fabsf(h2v.x-s2v.x);
            float re = fabsf(h0v.x-e0v.x) + fabsf(h1v.x-e1v.x) + fabsf(h2v.x-e2v.x);
            o4.x = sgnsel(rs, re);
        }
        {
            float rs = fabsf(h0v.y-s0v.y) + fabsf(h1v.y-s1v.y) + fabsf(h2v.y-s2v.y);
            float re = fabsf(h0v.y-e0v.y) + fabsf(h1v.y-e1v.y) + fabsf(h2v.y-e2v.y);
            o4.y = sgnsel(rs, re);
        }
        {
            float rs = fabsf(h0v.z-s0v.z) + fabsf(h1v.z-s1v.z) + fabsf(h2v.z-s2v.z);
            float re = fabsf(h0v.z-e0v.z) + fabsf(h1v.z-e1v.z) + fabsf(h2v.z-e2v.z);
            o4.z = sgnsel(rs, re);
        }
        {
            float rs = fabsf(h0v.w-s0v.w) + fabsf(h1v.w-s1v.w) + fabsf(h2v.w-s2v.w);
            float re = fabsf(h0v.w-e0v.w) + fabsf(h1v.w-e1v.w) + fabsf(h2v.w-e2v.w);
            o4.w = sgnsel(rs, re);
        }
        *(float4*)(&rt[row][4 * v]) = o4;
    }
    __syncthreads();

    // --- Phase 2: 3x3 unbiased local variance, 8 groups of 4 px per thread ---
    float lsum = 0.f, lsq = 0.f, lS = 0.f;
#pragma unroll
    for (int k = 0; k < 8; ++k) {
        const int g  = tid + k * NTHREADS;    // 0..2047
        const int r  = g >> 7;                // owned row 0..15 -> center smem row r+1
        const int cg = g & 127;
        const int c0 = cg << 2;

        float4 T = *(const float4*)(&rt[r    ][c0]);  // top
        float4 M = *(const float4*)(&rt[r + 1][c0]);  // middle (centers)
        float4 D = *(const float4*)(&rt[r + 2][c0]);  // bottom

        // column reflect at image edges: col -1 -> 1, col 512 -> 510
        const int lc = (cg == 0)   ? 1   : c0 - 1;
        const int rc = (cg == 127) ? 510 : c0 + 4;
        float tl = rt[r    ][lc], tr2 = rt[r    ][rc];
        float ml = rt[r + 1][lc], mr  = rt[r + 1][rc];
        float dl = rt[r + 2][lc], dr  = rt[r + 2][rc];

        // per-row sliding 3-sums over (l, v0..v3, r) for abs and square
        float A0[4], B0[4], A1[4], B1[4], A2[4], B2[4];
        {
            float pl = fabsf(tl), p0 = fabsf(T.x), p1 = fabsf(T.y),
                  p2 = fabsf(T.z), p3 = fabsf(T.w), pr = fabsf(tr2);
            A0[0]=pl+p0+p1; A0[1]=p0+p1+p2; A0[2]=p1+p2+p3; A0[3]=p2+p3+pr;
            B0[0]=pl*pl+p0*p0+p1*p1; B0[1]=p0*p0+p1*p1+p2*p2;
            B0[2]=p1*p1+p2*p2+p3*p3; B0[3]=p2*p2+p3*p3+pr*pr;
        }
        {
            float pl = fabsf(ml), p0 = fabsf(M.x), p1 = fabsf(M.y),
                  p2 = fabsf(M.z), p3 = fabsf(M.w), pr = fabsf(mr);
            A1[0]=pl+p0+p1; A1[1]=p0+p1+p2; A1[2]=p1+p2+p3; A1[3]=p2+p3+pr;
            B1[0]=pl*pl+p0*p0+p1*p1; B1[1]=p0*p0+p1*p1+p2*p2;
            B1[2]=p1*p1+p2*p2+p3*p3; B1[3]=p2*p2+p3*p3+pr*pr;
        }
        {
            float pl = fabsf(dl), p0 = fabsf(D.x), p1 = fabsf(D.y),
                  p2 = fabsf(D.z), p3 = fabsf(D.w), pr = fabsf(dr);
            A2[0]=pl+p0+p1; A2[1]=p0+p1+p2; A2[2]=p1+p2+p3; A2[3]=p2+p3+pr;
            B2[0]=pl*pl+p0*p0+p1*p1; B2[1]=p0*p0+p1*p1+p2*p2;
            B2[2]=p1*p1+p2*p2+p3*p3; B2[3]=p2*p2+p3*p3+pr*pr;
        }

        const float cen[4] = { M.x, M.y, M.z, M.w };
#pragma unroll
        for (int x = 0; x < 4; ++x) {
            float s  = A0[x] + A1[x] + A2[x];
            float sq = B0[x] + B1[x] + B2[x];
            float lv = (sq - s * s * (1.0f / 9.0f)) * (1.0f / 8.0f);
            float r4 = fabsf(cen[x]);
            lS   += signbit(cen[x]) ? 0.0f : fabsf(lv) * r4;
            lsum += r4;
            lsq  += r4 * r4;
        }
    }

    // --- Block reduction ------------------------------------------------------
    __shared__ float wsum[8], wsq[8], wS[8];
#pragma unroll
    for (int o = 16; o > 0; o >>= 1) {
        lsum += __shfl_down_sync(0xffffffffu, lsum, o);
        lsq  += __shfl_down_sync(0xffffffffu, lsq,  o);
        lS   += __shfl_down_sync(0xffffffffu, lS,   o);
    }
    const int warp = tid >> 5;
    const int lane = tid & 31;
    if (lane == 0) { wsum[warp] = lsum; wsq[warp] = lsq; wS[warp] = lS; }
    __syncthreads();

    __shared__ bool isLast;
    if (tid == 0) {
        float a = 0.f, c = 0.f, d = 0.f;
#pragma unroll
        for (int i = 0; i < 8; ++i) { a += wsum[i]; c += wsq[i]; d += wS[i]; }
        g_psum[bid] = a;
        g_psq[bid]  = c;
        g_pS[bid]   = d;
        __threadfence();
        unsigned prev = atomicAdd(&g_count, 1u);
        isLast = (prev == NBLK - 1);
    }
    __syncthreads();

    // --- Last block: per-batch patch weight + final loss -----------------------
    if (isLast) {
        if (tid == 0) g_count = 0;   // reset for next graph replay
        __shared__ float sres[Bn];
        // 8 warps, each handles 2 batches; 32 partials per batch (1 per lane).
#pragma unroll
        for (int j = 0; j < 2; ++j) {
            const int bb  = warp * 2 + j;
            const int idx = bb * 32 + lane;
            float s  = __ldcg(&g_psum[idx]);
            float sq = __ldcg(&g_psq[idx]);
            float S  = __ldcg(&g_pS[idx]);
#pragma unroll
            for (int o = 16; o > 0; o >>= 1) {
                s  += __shfl_down_sync(0xffffffffu, s,  o);
                sq += __shfl_down_sync(0xffffffffu, sq, o);
                S  += __shfl_down_sync(0xffffffffu, S,  o);
            }
            if (lane == 0) {
                const float n = (float)HW;
                float var = (sq - s * s / n) / (n - 1.0f);   // raw scale
                float w = (var > 0.0f) ? exp2f(0.2f * log2f(var)) : 0.0f;
                sres[bb] = w * S;
            }
        }
        __syncthreads();
        if (tid == 0) {
            float acc = 0.f;
#pragma unroll
            for (int i = 0; i < Bn; ++i) acc += sres[i];
            // loss = 255/NTOT * sum_b (k^2 var)^0.2 * k^3 S, k = 1/255
            //      = 255^(-2.4)/NTOT * sum_b var_raw^0.2 * S_raw
            double Kd = pow(255.0, -2.4) / (double)NTOT;
            out[0] = (float)((double)acc * Kd);
        }
    }
}

// ---------------------------------------------------------------------------
extern "C" void kernel_launch(void* const* d_in, const int* in_sizes, int n_in,
                              void* d_out, int out_size) {
    const float* sr    = (const float*)d_in[0];
    const float* srema = (const float*)d_in[1];
    const float* hr    = (const float*)d_in[2];
    float* out = (float*)d_out;

    fused_kernel<<<NBLK, NTHREADS>>>(sr, srema, hr, out);
}